// round 12
// baseline (speedup 1.0000x reference)
#include <cuda_runtime.h>
#include <cuda_bf16.h>
#include <math.h>
#include <stdint.h>

// ---------------- problem constants ----------------
#define DMODEL 1024
#define DINNER 2048
#define DSTATE 16
#define DTRANK 64
#define XDBC   96        // DTRANK + 2*DSTATE
#define NB     2
#define NT     4096
#define NTOK   (NB*NT)   // 8192
#define EPSRMS 1e-5f
#define WX_SPLIT 8

// ---------------- scratch (static device globals; no runtime alloc) ----------------
__device__ __nv_bfloat16 g_xn_bf[(size_t)NTOK * DMODEL];
__device__ float g_xr[(size_t)NTOK * 2 * DINNER];      // (u_raw | res)
__device__ float g_u [(size_t)NTOK * DINNER];
__device__ float g_xdbc[(size_t)NTOK * XDBC];          // (dt | B | C)
__device__ float g_delta[(size_t)NTOK * DINNER];
__device__ __nv_bfloat16 g_y_bf[(size_t)NTOK * DINNER];
__device__ float g_part[(size_t)WX_SPLIT * NTOK * XDBC];
__device__ __nv_bfloat16 g_winT[(size_t)(2*DINNER) * DMODEL];   // [4096][1024]
__device__ __nv_bfloat16 g_woutT[(size_t)DMODEL * DINNER];      // [1024][2048]

// ---------------- helpers ----------------
__device__ __forceinline__ float to_tf32(float x) {
    float r;
    asm("cvt.rna.tf32.f32 %0, %1;" : "=f"(r) : "f"(x));
    return r;
}
__device__ __forceinline__ void mma_tf32(float* c, const float* a, const float* b) {
    asm volatile(
        "mma.sync.aligned.m16n8k8.row.col.f32.tf32.tf32.f32 "
        "{%0,%1,%2,%3}, {%4,%5,%6,%7}, {%8,%9}, {%0,%1,%2,%3};\n"
        : "+f"(c[0]), "+f"(c[1]), "+f"(c[2]), "+f"(c[3])
        : "r"(__float_as_uint(a[0])), "r"(__float_as_uint(a[1])),
          "r"(__float_as_uint(a[2])), "r"(__float_as_uint(a[3])),
          "r"(__float_as_uint(b[0])), "r"(__float_as_uint(b[1])));
}
// bf16 m16n8k16: 2x FLOP per instruction vs tf32 m16n8k8
__device__ __forceinline__ void mma_bf16(float* c, const uint32_t* a, const uint32_t* b) {
    asm volatile(
        "mma.sync.aligned.m16n8k16.row.col.f32.bf16.bf16.f32 "
        "{%0,%1,%2,%3}, {%4,%5,%6,%7}, {%8,%9}, {%0,%1,%2,%3};\n"
        : "+f"(c[0]), "+f"(c[1]), "+f"(c[2]), "+f"(c[3])
        : "r"(a[0]), "r"(a[1]), "r"(a[2]), "r"(a[3]),
          "r"(b[0]), "r"(b[1]));
}
__device__ __forceinline__ float softplusf(float v) {
    return (v > 20.0f) ? v : log1pf(expf(v));
}

// ---------------- rmsnorm: one block per token, bf16 output ----------------
__global__ __launch_bounds__(256) void rms_kernel(const float* __restrict__ x,
                                                  const float* __restrict__ w,
                                                  __nv_bfloat16* __restrict__ xn)
{
    int row = blockIdx.x;
    const float4* xin = (const float4*)(x + (size_t)row * DMODEL);
    float4 v = xin[threadIdx.x];
    float ss = v.x*v.x + v.y*v.y + v.z*v.z + v.w*v.w;
    #pragma unroll
    for (int o = 16; o; o >>= 1) ss += __shfl_xor_sync(0xffffffffu, ss, o);
    __shared__ float sred[8];
    if ((threadIdx.x & 31) == 0) sred[threadIdx.x >> 5] = ss;
    __syncthreads();
    if (threadIdx.x < 8) {
        float t = sred[threadIdx.x];
        #pragma unroll
        for (int o = 4; o; o >>= 1) t += __shfl_xor_sync(0xffu, t, o);
        if (threadIdx.x == 0) sred[0] = t;
    }
    __syncthreads();
    float scale = rsqrtf(sred[0] * (1.0f / DMODEL) + EPSRMS);
    float4 wv = ((const float4*)w)[threadIdx.x];
    __nv_bfloat162 b0, b1;
    b0.x = __float2bfloat16(v.x * scale * wv.x);
    b0.y = __float2bfloat16(v.y * scale * wv.y);
    b1.x = __float2bfloat16(v.z * scale * wv.z);
    b1.y = __float2bfloat16(v.w * scale * wv.w);
    __nv_bfloat162* po = (__nv_bfloat162*)(xn + (size_t)row * DMODEL);
    po[2 * threadIdx.x]     = b0;
    po[2 * threadIdx.x + 1] = b1;
}

// ---------------- transpose + fp32->bf16: W[R][Ncols] -> WT[Ncols][R] ----------------
__global__ __launch_bounds__(256) void transpose_bf(const float* __restrict__ W,
                                                    __nv_bfloat16* __restrict__ WT,
                                                    int R, int Ncols)
{
    __shared__ float t[32][33];
    int tx = threadIdx.x & 31, ty = threadIdx.x >> 5;
    int c0 = blockIdx.x * 32, r0 = blockIdx.y * 32;
    #pragma unroll
    for (int i = 0; i < 4; i++) {
        t[ty + i * 8][tx] = W[(long)(r0 + ty + i * 8) * Ncols + c0 + tx];
    }
    __syncthreads();
    #pragma unroll
    for (int i = 0; i < 4; i++) {
        WT[(long)(c0 + ty + i * 8) * R + r0 + tx] = __float2bfloat16(t[tx][ty + i * 8]);
    }
}

// ---------------- bf16 mma.sync GEMM: C[M,N] = A[M,K] @ BT[N,K]^T (+ residual) ----------------
// 128x128 block tile, 256 threads / 8 warps (warp tile 32x64), K tiles of 32,
// double-buffered smem of bf16x2-packed operands; both operands staged from
// row-major [rows][K] bf16 with identical mapping. XOR swizzle (group kk>>2,
// stride 136 == 8 mod 32) keeps STS and all fragment LDS conflict-free.
// EPI: 0 = none, 1 = +Aux[r,c] residual.
template<int EPI>
__global__ __launch_bounds__(256) void gemm_bf(const __nv_bfloat16* __restrict__ A,
                                               const __nv_bfloat16* __restrict__ B,
                                               const float* __restrict__ Aux,
                                               float* __restrict__ C,
                                               int K, int N)
{
    __shared__ uint32_t As[2][16][136];   // [kk = k/2][m], bf16x2 (k, k+1)
    __shared__ uint32_t Bs[2][16][136];   // [kk][n]
    const int tid = threadIdx.x;
    const int col0 = blockIdx.x * 128;
    const long row0 = (long)blockIdx.y * 128;
    const int lane = tid & 31, warp = tid >> 5;
    const int mW = (warp >> 1) * 32, nW = (warp & 1) * 64;
    const int gid = lane >> 2, tg = lane & 3;

    // staging: warps 0-3 stage A, warps 4-7 stage B; 4 uint4 per thread
    const int op = tid >> 7;
    const int s  = tid & 127;
    const int srow = s >> 2;              // 0..31 (+ 32*i)
    const int seg  = s & 3;               // 16B segment (8 bf16 = 4 kk)
    const __nv_bfloat16* base = op ? (B + (long)col0 * K) : (A + row0 * K);

    uint4 pv[4];
    #pragma unroll
    for (int i = 0; i < 4; i++)
        pv[i] = *(const uint4*)(base + (long)(srow + i * 32) * K + seg * 8);

    float acc[2][8][4];
    #pragma unroll
    for (int mi = 0; mi < 2; mi++)
        #pragma unroll
        for (int ni = 0; ni < 8; ni++)
            #pragma unroll
            for (int j = 0; j < 4; j++) acc[mi][ni][j] = 0.f;

    const int KT = K >> 5;
    int buf = 0;
    // stage 0 store
    #pragma unroll
    for (int i = 0; i < 4; i++) {
        int r = (srow + i * 32) ^ (seg << 3);
        const uint32_t* q = (const uint32_t*)&pv[i];
        if (op == 0) {
            #pragma unroll
            for (int j = 0; j < 4; j++) As[0][seg * 4 + j][r] = q[j];
        } else {
            #pragma unroll
            for (int j = 0; j < 4; j++) Bs[0][seg * 4 + j][r] = q[j];
        }
    }
    __syncthreads();

    for (int kt = 0; kt < KT; kt++) {
        if (kt + 1 < KT) {
            #pragma unroll
            for (int i = 0; i < 4; i++)
                pv[i] = *(const uint4*)(base + (long)(srow + i * 32) * K
                                        + (kt + 1) * 32 + seg * 8);
        }
        #pragma unroll
        for (int ks = 0; ks < 2; ks++) {
            const int kL = ks * 8 + tg;       // group 2ks   -> XOR 16*ks
            const int kH = ks * 8 + tg + 4;   // group 2ks+1 -> XOR 16*ks+8
            const int xL = 16 * ks, xH = 16 * ks + 8;
            uint32_t a[2][4], b[8][2];
            #pragma unroll
            for (int mi = 0; mi < 2; mi++) {
                int m = mW + mi * 16 + gid;
                a[mi][0] = As[buf][kL][m ^ xL];
                a[mi][1] = As[buf][kL][(m + 8) ^ xL];
                a[mi][2] = As[buf][kH][m ^ xH];
                a[mi][3] = As[buf][kH][(m + 8) ^ xH];
            }
            #pragma unroll
            for (int ni = 0; ni < 8; ni++) {
                int n = nW + ni * 8 + gid;
                b[ni][0] = Bs[buf][kL][n ^ xL];
                b[ni][1] = Bs[buf][kH][n ^ xH];
            }
            #pragma unroll
            for (int mi = 0; mi < 2; mi++)
                #pragma unroll
                for (int ni = 0; ni < 8; ni++)
                    mma_bf16(acc[mi][ni], a[mi], b[ni]);
        }
        if (kt + 1 < KT) {
            int nb = buf ^ 1;
            #pragma unroll
            for (int i = 0; i < 4; i++) {
                int r = (srow + i * 32) ^ (seg << 3);
                const uint32_t* q = (const uint32_t*)&pv[i];
                if (op == 0) {
                    #pragma unroll
                    for (int j = 0; j < 4; j++) As[nb][seg * 4 + j][r] = q[j];
                } else {
                    #pragma unroll
                    for (int j = 0; j < 4; j++) Bs[nb][seg * 4 + j][r] = q[j];
                }
            }
            __syncthreads();
            buf = nb;
        }
    }

    // epilogue: c0,c1 -> (row, 2tg..2tg+1); c2,c3 -> (row+8, same cols)
    #pragma unroll
    for (int mi = 0; mi < 2; mi++) {
        long r = row0 + mW + mi * 16 + gid;
        #pragma unroll
        for (int ni = 0; ni < 8; ni++) {
            long c = col0 + nW + ni * 8 + 2 * tg;
            float2 v0 = make_float2(acc[mi][ni][0], acc[mi][ni][1]);
            float2 v1 = make_float2(acc[mi][ni][2], acc[mi][ni][3]);
            if (EPI == 1) {
                float2 r0 = *(const float2*)(Aux + r * N + c);
                float2 r1 = *(const float2*)(Aux + (r + 8) * N + c);
                v0.x += r0.x; v0.y += r0.y; v1.x += r1.x; v1.y += r1.y;
            }
            *(float2*)(C + r * N + c)       = v0;
            *(float2*)(C + (r + 8) * N + c) = v1;
        }
    }
}

// ---------------- depthwise causal conv (K=4) + bias + silu ----------------
__global__ __launch_bounds__(256) void conv_kernel(const float* __restrict__ xr,
                                                   const float* __restrict__ cw,
                                                   const float* __restrict__ cb,
                                                   float* __restrict__ u)
{
    int idx = blockIdx.x * 256 + threadIdx.x;
    int d   = idx & (DINNER - 1);
    int tok = idx >> 11;
    int t   = tok & (NT - 1);
    const float* p = xr + (size_t)tok * (2*DINNER) + d;
    float w0 = cw[d*4+0], w1 = cw[d*4+1], w2 = cw[d*4+2], w3 = cw[d*4+3];
    float acc = cb[d] + w3 * p[0];
    if (t >= 1) acc = fmaf(w2, p[-(2*DINNER)],   acc);
    if (t >= 2) acc = fmaf(w1, p[-2*(2*DINNER)], acc);
    if (t >= 3) acc = fmaf(w0, p[-3*(2*DINNER)], acc);
    u[idx] = acc / (1.0f + __expf(-acc));
}

// ---------------- tf32 mma.sync GEMM (dt path: K=64, bias+softplus epilogue) ----------------
__global__ __launch_bounds__(256) void gemm_dt_tc(const float* __restrict__ A,
                                                  const float* __restrict__ B,
                                                  const float* __restrict__ Aux,
                                                  float* __restrict__ C,
                                                  int K, int N, int lda)
{
    __shared__ float As[2][16][136];
    __shared__ float Bs[2][16][136];
    const int tid = threadIdx.x;
    const int col0 = blockIdx.x * 128;
    const long row0 = (long)blockIdx.y * 128;
    const int lane = tid & 31, warp = tid >> 5;
    const int mW = (warp >> 1) * 32, nW = (warp & 1) * 64;
    const int gid = lane >> 2, tg = lane & 3;

    const int arow = tid >> 2;
    const int acg  = tid & 3;
    const float* Ap = A + (row0 + arow) * (long)lda + acg * 4;
    const int bk  = tid >> 5;
    const int bn4 = tid & 31;
    const float* Bp = B + (long)bk * N + col0 + bn4 * 4;

    float4 pa[2], pb[2];
    pa[0] = *(const float4*)(Ap);
    pa[1] = *(const float4*)(Ap + 64 * (long)lda);
    pb[0] = *(const float4*)(Bp);
    pb[1] = *(const float4*)(Bp + 8 * (long)N);

    float acc[2][8][4];
    #pragma unroll
    for (int mi = 0; mi < 2; mi++)
        #pragma unroll
        for (int ni = 0; ni < 8; ni++)
            #pragma unroll
            for (int j = 0; j < 4; j++) acc[mi][ni][j] = 0.f;

    const int KT = K >> 4;
    int buf = 0;
    #pragma unroll
    for (int i = 0; i < 2; i++) {
        int rr = arow + i * 64;
        float v[4] = {pa[i].x, pa[i].y, pa[i].z, pa[i].w};
        #pragma unroll
        for (int j = 0; j < 4; j++) {
            int c = acg * 4 + j;
            As[0][c][rr ^ (((c >> 2) & 3) << 3)] = to_tf32(v[j]);
        }
        float4 q = pb[i];
        q.x = to_tf32(q.x); q.y = to_tf32(q.y);
        q.z = to_tf32(q.z); q.w = to_tf32(q.w);
        *(float4*)&Bs[0][bk + i * 8][bn4 * 4] = q;
    }
    __syncthreads();

    for (int kt = 0; kt < KT; kt++) {
        if (kt + 1 < KT) {
            pa[0] = *(const float4*)(Ap + (kt + 1) * 16);
            pa[1] = *(const float4*)(Ap + (kt + 1) * 16 + 64 * (long)lda);
            pb[0] = *(const float4*)(Bp + (long)((kt + 1) * 16) * N);
            pb[1] = *(const float4*)(Bp + (long)((kt + 1) * 16 + 8) * N);
        }
        #pragma unroll
        for (int ks = 0; ks < 2; ks++) {
            const int k0 = ks * 8;
            const int kA = k0 + tg, kB = k0 + tg + 4;
            const int sA = ((kA >> 2) & 3) << 3;
            const int sB = ((kB >> 2) & 3) << 3;
            float a[2][4], b[8][2];
            #pragma unroll
            for (int mi = 0; mi < 2; mi++) {
                int m = mW + mi * 16 + gid;
                a[mi][0] = As[buf][kA][m ^ sA];
                a[mi][1] = As[buf][kA][(m + 8) ^ sA];
                a[mi][2] = As[buf][kB][m ^ sB];
                a[mi][3] = As[buf][kB][(m + 8) ^ sB];
            }
            #pragma unroll
            for (int ni = 0; ni < 8; ni++) {
                int n = nW + ni * 8 + gid;
                b[ni][0] = Bs[buf][kA][n];
                b[ni][1] = Bs[buf][kB][n];
            }
            #pragma unroll
            for (int mi = 0; mi < 2; mi++)
                #pragma unroll
                for (int ni = 0; ni < 8; ni++)
                    mma_tf32(acc[mi][ni], a[mi], b[ni]);
        }
        if (kt + 1 < KT) {
            int nb = buf ^ 1;
            #pragma unroll
            for (int i = 0; i < 2; i++) {
                int rr = arow + i * 64;
                float v[4] = {pa[i].x, pa[i].y, pa[i].z, pa[i].w};
                #pragma unroll
                for (int j = 0; j < 4; j++) {
                    int c = acg * 4 + j;
                    As[nb][c][rr ^ (((c >> 2) & 3) << 3)] = to_tf32(v[j]);
                }
                float4 q = pb[i];
                q.x = to_tf32(q.x); q.y = to_tf32(q.y);
                q.z = to_tf32(q.z); q.w = to_tf32(q.w);
                *(float4*)&Bs[nb][bk + i * 8][bn4 * 4] = q;
            }
            __syncthreads();
            buf = nb;
        }
    }

    #pragma unroll
    for (int mi = 0; mi < 2; mi++) {
        long rr = row0 + mW + mi * 16 + gid;
        #pragma unroll
        for (int ni = 0; ni < 8; ni++) {
            long c = col0 + nW + ni * 8 + 2 * tg;
            float2 v0 = make_float2(acc[mi][ni][0], acc[mi][ni][1]);
            float2 v1 = make_float2(acc[mi][ni][2], acc[mi][ni][3]);
            float b0 = Aux[c], b1 = Aux[c + 1];
            v0.x = softplusf(v0.x + b0); v0.y = softplusf(v0.y + b1);
            v1.x = softplusf(v1.x + b0); v1.y = softplusf(v1.y + b1);
            *(float2*)(C + rr * N + c)       = v0;
            *(float2*)(C + (rr + 8) * N + c) = v1;
        }
    }
}

// ---------------- gemm_wx: tf32 split-K tensor GEMM ----------------
__global__ __launch_bounds__(128) void gemm_wx_tc(const float* __restrict__ A,
                                                  const float* __restrict__ W,
                                                  float* __restrict__ P)
{
    __shared__ float As[2][16][136];
    __shared__ float Ws[2][16][104];
    const int tid = threadIdx.x;
    const long row0 = (long)blockIdx.x * 128;
    const int kblk = blockIdx.y;
    const int lane = tid & 31, warp = tid >> 5;
    const int mW = (warp >> 1) * 64, nW = (warp & 1) * 48;
    const int gid = lane >> 2, tg = lane & 3;

    const int arow = tid >> 2;
    const int acg  = tid & 3;
    const float* Ap = A + (row0 + arow) * (long)DINNER + kblk * 256 + acg * 4;
    int wr[3], wc[3];
    #pragma unroll
    for (int i = 0; i < 3; i++) {
        int idx = tid + i * 128;
        wr[i] = idx / 24; wc[i] = idx - wr[i] * 24;
    }
    const float* Wp = W + (long)(kblk * 256) * XDBC;

    float4 pa[4], pw[3];
    #pragma unroll
    for (int i = 0; i < 4; i++) pa[i] = *(const float4*)(Ap + (long)i * 32 * DINNER);
    #pragma unroll
    for (int i = 0; i < 3; i++) pw[i] = *(const float4*)(Wp + (long)wr[i] * XDBC + wc[i] * 4);

    float acc[4][6][4];
    #pragma unroll
    for (int mi = 0; mi < 4; mi++)
        #pragma unroll
        for (int ni = 0; ni < 6; ni++)
            #pragma unroll
            for (int j = 0; j < 4; j++) acc[mi][ni][j] = 0.f;

    int buf = 0;
    #pragma unroll
    for (int i = 0; i < 4; i++) {
        int rr = arow + i * 32;
        float v[4] = {pa[i].x, pa[i].y, pa[i].z, pa[i].w};
        #pragma unroll
        for (int j = 0; j < 4; j++) {
            int c = acg * 4 + j;
            As[0][c][rr ^ (((c >> 2) & 3) << 3)] = to_tf32(v[j]);
        }
    }
    #pragma unroll
    for (int i = 0; i < 3; i++) {
        float4 q = pw[i];
        q.x = to_tf32(q.x); q.y = to_tf32(q.y);
        q.z = to_tf32(q.z); q.w = to_tf32(q.w);
        *(float4*)&Ws[0][wr[i]][wc[i] * 4] = q;
    }
    __syncthreads();

    const int KT = 256 / 16;
    for (int kt = 0; kt < KT; kt++) {
        if (kt + 1 < KT) {
            #pragma unroll
            for (int i = 0; i < 4; i++)
                pa[i] = *(const float4*)(Ap + (kt + 1) * 16 + (long)i * 32 * DINNER);
            #pragma unroll
            for (int i = 0; i < 3; i++)
                pw[i] = *(const float4*)(Wp + (long)((kt + 1) * 16 + wr[i]) * XDBC + wc[i] * 4);
        }
        #pragma unroll
        for (int ks = 0; ks < 2; ks++) {
            const int k0 = ks * 8;
            const int kA = k0 + tg, kB = k0 + tg + 4;
            const int sA = ((kA >> 2) & 3) << 3;
            const int sB = ((kB >> 2) & 3) << 3;
            float a[4][4], b[6][2];
            #pragma unroll
            for (int mi = 0; mi < 4; mi++) {
                int m = mW + mi * 16 + gid;
                a[mi][0] = As[buf][kA][m ^ sA];
                a[mi][1] = As[buf][kA][(m + 8) ^ sA];
                a[mi][2] = As[buf][kB][m ^ sB];
                a[mi][3] = As[buf][kB][(m + 8) ^ sB];
            }
            #pragma unroll
            for (int ni = 0; ni < 6; ni++) {
                int n = nW + ni * 8 + gid;
                b[ni][0] = Ws[buf][kA][n];
                b[ni][1] = Ws[buf][kB][n];
            }
            #pragma unroll
            for (int mi = 0; mi < 4; mi++)
                #pragma unroll
                for (int ni = 0; ni < 6; ni++)
                    mma_tf32(acc[mi][ni], a[mi], b[ni]);
        }
        if (kt + 1 < KT) {
            int nb = buf ^ 1;
            #pragma unroll
            for (int i = 0; i < 4; i++) {
                int rr = arow + i * 32;
                float v[4] = {pa[i].x, pa[i].y, pa[i].z, pa[i].w};
                #pragma unroll
                for (int j = 0; j < 4; j++) {
                    int c = acg * 4 + j;
                    As[nb][c][rr ^ (((c >> 2) & 3) << 3)] = to_tf32(v[j]);
                }
            }
            #pragma unroll
            for (int i = 0; i < 3; i++) {
                float4 q = pw[i];
                q.x = to_tf32(q.x); q.y = to_tf32(q.y);
                q.z = to_tf32(q.z); q.w = to_tf32(q.w);
                *(float4*)&Ws[nb][wr[i]][wc[i] * 4] = q;
            }
            __syncthreads();
            buf = nb;
        }
    }

    float* Pb = P + (size_t)kblk * NTOK * XDBC;
    #pragma unroll
    for (int mi = 0; mi < 4; mi++) {
        long rr = row0 + mW + mi * 16 + gid;
        #pragma unroll
        for (int ni = 0; ni < 6; ni++) {
            long c = nW + ni * 8 + 2 * tg;
            *(float2*)(Pb + rr * XDBC + c)       = make_float2(acc[mi][ni][0], acc[mi][ni][1]);
            *(float2*)(Pb + (rr + 8) * XDBC + c) = make_float2(acc[mi][ni][2], acc[mi][ni][3]);
        }
    }
}

__global__ __launch_bounds__(256) void wx_reduce(const float* __restrict__ P,
                                                 float* __restrict__ C)
{
    size_t i = (size_t)blockIdx.x * 256 + threadIdx.x;
    const float4* p = (const float4*)P;
    const size_t stride = (size_t)NTOK * XDBC / 4;
    float4 s = p[i];
    #pragma unroll
    for (int k = 1; k < WX_SPLIT; k++) {
        float4 t = p[i + (size_t)k * stride];
        s.x += t.x; s.y += t.y; s.z += t.z; s.w += t.w;
    }
    ((float4*)C)[i] = s;
}

// ---------------- selective scan (bf16 y output) ----------------
__global__ __launch_bounds__(128) void scan_kernel(const float* __restrict__ delta,
                                                   const float* __restrict__ u,
                                                   const float* __restrict__ xdbc,
                                                   const float* __restrict__ xr,
                                                   const float* __restrict__ A_log,
                                                   const float* __restrict__ Dp,
                                                   __nv_bfloat16* __restrict__ y)
{
    __shared__ float sd[64][8], su[64][8], sres[64][8], ybuf[64][8];
    __shared__ float sbc[64][32];
    __shared__ float sD[8];

    int b     = blockIdx.x >> 8;
    int dbase = (blockIdx.x & 255) * 8;
    int tid   = threadIdx.x;
    int lane  = tid & 31, w = tid >> 5;
    int dloc  = 2 * w + (lane >> 4);
    int n     = lane & 15;
    int d     = dbase + dloc;

    float Ac = -expf(A_log[d * DSTATE + n]);
    if (tid < 8) sD[tid] = Dp[dbase + tid];

    float h = 0.0f;
    long tokbase = (long)b * NT;

    for (int c = 0; c < NT / 64; c++) {
        int t0 = c * 64;
        for (int i = tid; i < 512; i += 128) {
            int tl = i >> 3, dl = i & 7;
            long g = (tokbase + t0 + tl) * (long)DINNER + dbase + dl;
            sd[tl][dl]   = delta[g];
            su[tl][dl]   = u[g];
            sres[tl][dl] = xr[(tokbase + t0 + tl) * (long)(2*DINNER) + DINNER + dbase + dl];
        }
        for (int i = tid; i < 2048; i += 128) {
            int tl = i >> 5, cc = i & 31;
            sbc[tl][cc] = xdbc[(tokbase + t0 + tl) * (long)XDBC + DTRANK + cc];
        }
        __syncthreads();

        #pragma unroll 4
        for (int tl = 0; tl < 64; tl++) {
            float dlt = sd[tl][dloc];
            float uu  = su[tl][dloc];
            float a   = __expf(dlt * Ac);
            h = fmaf(a, h, dlt * uu * sbc[tl][n]);
            float p = h * sbc[tl][16 + n];
            p += __shfl_xor_sync(0xffffffffu, p, 8);
            p += __shfl_xor_sync(0xffffffffu, p, 4);
            p += __shfl_xor_sync(0xffffffffu, p, 2);
            p += __shfl_xor_sync(0xffffffffu, p, 1);
            if (n == 0) ybuf[tl][dloc] = p;
        }
        __syncthreads();

        for (int i = tid; i < 512; i += 128) {
            int tl = i >> 3, dl = i & 7;
            float uu = su[tl][dl];
            float r  = sres[tl][dl];
            float yy = (ybuf[tl][dl] + uu * sD[dl]) * (r / (1.0f + __expf(-r)));
            y[(tokbase + t0 + tl) * (long)DINNER + dbase + dl] = __float2bfloat16(yy);
        }
        __syncthreads();
    }
}

// ---------------- launch ----------------
extern "C" void kernel_launch(void* const* d_in, const int* in_sizes, int n_in,
                              void* d_out, int out_size)
{
    (void)in_sizes; (void)n_in; (void)out_size;
    const float* x      = (const float*)d_in[0];
    const float* norm_w = (const float*)d_in[1];
    const float* w_in   = (const float*)d_in[2];
    const float* conv_w = (const float*)d_in[3];
    const float* conv_b = (const float*)d_in[4];
    const float* w_x    = (const float*)d_in[5];
    const float* w_dt   = (const float*)d_in[6];
    const float* b_dt   = (const float*)d_in[7];
    const float* A_log  = (const float*)d_in[8];
    const float* Dp     = (const float*)d_in[9];
    const float* w_out  = (const float*)d_in[10];
    float* out = (float*)d_out;

    __nv_bfloat16* p_xnbf  = 0;
    __nv_bfloat16* p_ybf   = 0;
    __nv_bfloat16* p_winT  = 0;
    __nv_bfloat16* p_woutT = 0;
    float* p_xr    = 0;
    float* p_u     = 0;
    float* p_xdbc  = 0;
    float* p_delta = 0;
    float* p_part  = 0;
    cudaGetSymbolAddress((void**)&p_xnbf,  g_xn_bf);
    cudaGetSymbolAddress((void**)&p_xr,    g_xr);
    cudaGetSymbolAddress((void**)&p_u,     g_u);
    cudaGetSymbolAddress((void**)&p_xdbc,  g_xdbc);
    cudaGetSymbolAddress((void**)&p_delta, g_delta);
    cudaGetSymbolAddress((void**)&p_ybf,   g_y_bf);
    cudaGetSymbolAddress((void**)&p_part,  g_part);
    cudaGetSymbolAddress((void**)&p_winT,  g_winT);
    cudaGetSymbolAddress((void**)&p_woutT, g_woutT);

    // 1. rmsnorm -> bf16 xn
    rms_kernel<<<NTOK, 256>>>(x, norm_w, p_xnbf);
    // 1b. weight transposes -> bf16 [N][K]
    transpose_bf<<<dim3((2*DINNER)/32, DMODEL/32), 256>>>(w_in, p_winT, DMODEL, 2*DINNER);
    transpose_bf<<<dim3(DMODEL/32, DINNER/32), 256>>>(w_out, p_woutT, DINNER, DMODEL);
    // 2. xr = xn @ w_in   [bf16 mma.sync m16n8k16]
    gemm_bf<0><<<dim3((2*DINNER)/128, NTOK/128), 256>>>(
        p_xnbf, p_winT, (const float*)0, p_xr, DMODEL, 2*DINNER);
    // 3. u = silu(depthwise_conv(xr[:, :2048]) + conv_b)
    conv_kernel<<<(NTOK*DINNER)/256, 256>>>(p_xr, conv_w, conv_b, p_u);
    // 4. xdbc = u @ w_x   [tf32 split-K + reduce]
    gemm_wx_tc<<<dim3(NTOK/128, WX_SPLIT), 128>>>(p_u, w_x, p_part);
    wx_reduce<<<(NTOK*XDBC/4)/256, 256>>>(p_part, p_xdbc);
    // 5. delta = softplus(dt @ w_dt + b_dt)   [tf32 mma, K=64]
    gemm_dt_tc<<<dim3(DINNER/128, NTOK/128), 256>>>(p_xdbc, w_dt, b_dt, p_delta, DTRANK, DINNER, XDBC);
    // 6. selective scan + gating -> bf16 y
    scan_kernel<<<NB*256, 128>>>(p_delta, p_u, p_xdbc, p_xr, A_log, Dp, p_ybf);
    // 7. out = y @ w_out + x   [bf16 mma.sync + residual]
    gemm_bf<1><<<dim3(DMODEL/128, NTOK/128), 256>>>(
        p_ybf, p_woutT, x, out, DINNER, DMODEL);
}

// round 13
// speedup vs baseline: 1.5113x; 1.5113x over previous
#include <cuda_runtime.h>
#include <cuda_bf16.h>
#include <math.h>
#include <stdint.h>

// ---------------- problem constants ----------------
#define DMODEL 1024
#define DINNER 2048
#define DSTATE 16
#define DTRANK 64
#define XDBC   96        // DTRANK + 2*DSTATE
#define NB     2
#define NT     4096
#define NTOK   (NB*NT)   // 8192
#define EPSRMS 1e-5f
#define WX_SPLIT 8

// ---------------- scratch (static device globals; no runtime alloc) ----------------
__device__ __align__(16) __nv_bfloat16 g_xn_bf[(size_t)NTOK * DMODEL];
__device__ float g_xr[(size_t)NTOK * 2 * DINNER];      // (u_raw | res)
__device__ float g_u [(size_t)NTOK * DINNER];
__device__ float g_xdbc[(size_t)NTOK * XDBC];          // (dt | B | C)
__device__ float g_delta[(size_t)NTOK * DINNER];
__device__ __align__(16) __nv_bfloat16 g_y_bf[(size_t)NTOK * DINNER];
__device__ float g_part[(size_t)WX_SPLIT * NTOK * XDBC];
__device__ __align__(16) __nv_bfloat16 g_winT[(size_t)(2*DINNER) * DMODEL];   // [4096][1024]
__device__ __align__(16) __nv_bfloat16 g_woutT[(size_t)DMODEL * DINNER];      // [1024][2048]

// ---------------- helpers ----------------
__device__ __forceinline__ uint32_t smem_to_u32(const void* smem_ptr) {
    uint32_t addr;
    asm("{ .reg .u64 tmp; cvta.to.shared.u64 tmp, %1; cvt.u32.u64 %0, tmp; }"
        : "=r"(addr) : "l"(smem_ptr));
    return addr;
}
__device__ __forceinline__ float to_tf32(float x) {
    float r;
    asm("cvt.rna.tf32.f32 %0, %1;" : "=f"(r) : "f"(x));
    return r;
}
__device__ __forceinline__ void mma_tf32(float* c, const float* a, const float* b) {
    asm volatile(
        "mma.sync.aligned.m16n8k8.row.col.f32.tf32.tf32.f32 "
        "{%0,%1,%2,%3}, {%4,%5,%6,%7}, {%8,%9}, {%0,%1,%2,%3};\n"
        : "+f"(c[0]), "+f"(c[1]), "+f"(c[2]), "+f"(c[3])
        : "r"(__float_as_uint(a[0])), "r"(__float_as_uint(a[1])),
          "r"(__float_as_uint(a[2])), "r"(__float_as_uint(a[3])),
          "r"(__float_as_uint(b[0])), "r"(__float_as_uint(b[1])));
}
__device__ __forceinline__ void mma_bf16(float* c, const uint32_t* a, const uint32_t* b) {
    asm volatile(
        "mma.sync.aligned.m16n8k16.row.col.f32.bf16.bf16.f32 "
        "{%0,%1,%2,%3}, {%4,%5,%6,%7}, {%8,%9}, {%0,%1,%2,%3};\n"
        : "+f"(c[0]), "+f"(c[1]), "+f"(c[2]), "+f"(c[3])
        : "r"(a[0]), "r"(a[1]), "r"(a[2]), "r"(a[3]),
          "r"(b[0]), "r"(b[1]));
}
#define LDSM_X4(r0, r1, r2, r3, addr) \
    asm volatile("ldmatrix.sync.aligned.m8n8.x4.shared.b16 {%0,%1,%2,%3}, [%4];" \
        : "=r"(r0), "=r"(r1), "=r"(r2), "=r"(r3) : "r"(addr))

__device__ __forceinline__ float softplusf(float v) {
    return (v > 20.0f) ? v : log1pf(expf(v));
}

// ---------------- rmsnorm: one block per token, bf16 output ----------------
__global__ __launch_bounds__(256) void rms_kernel(const float* __restrict__ x,
                                                  const float* __restrict__ w,
                                                  __nv_bfloat16* __restrict__ xn)
{
    int row = blockIdx.x;
    const float4* xin = (const float4*)(x + (size_t)row * DMODEL);
    float4 v = xin[threadIdx.x];
    float ss = v.x*v.x + v.y*v.y + v.z*v.z + v.w*v.w;
    #pragma unroll
    for (int o = 16; o; o >>= 1) ss += __shfl_xor_sync(0xffffffffu, ss, o);
    __shared__ float sred[8];
    if ((threadIdx.x & 31) == 0) sred[threadIdx.x >> 5] = ss;
    __syncthreads();
    if (threadIdx.x < 8) {
        float t = sred[threadIdx.x];
        #pragma unroll
        for (int o = 4; o; o >>= 1) t += __shfl_xor_sync(0xffu, t, o);
        if (threadIdx.x == 0) sred[0] = t;
    }
    __syncthreads();
    float scale = rsqrtf(sred[0] * (1.0f / DMODEL) + EPSRMS);
    float4 wv = ((const float4*)w)[threadIdx.x];
    __nv_bfloat162 b0, b1;
    b0.x = __float2bfloat16(v.x * scale * wv.x);
    b0.y = __float2bfloat16(v.y * scale * wv.y);
    b1.x = __float2bfloat16(v.z * scale * wv.z);
    b1.y = __float2bfloat16(v.w * scale * wv.w);
    __nv_bfloat162* po = (__nv_bfloat162*)(xn + (size_t)row * DMODEL);
    po[2 * threadIdx.x]     = b0;
    po[2 * threadIdx.x + 1] = b1;
}

// ---------------- transpose + fp32->bf16: W[R][Ncols] -> WT[Ncols][R] ----------------
__global__ __launch_bounds__(256) void transpose_bf(const float* __restrict__ W,
                                                    __nv_bfloat16* __restrict__ WT,
                                                    int R, int Ncols)
{
    __shared__ float t[32][33];
    int tx = threadIdx.x & 31, ty = threadIdx.x >> 5;
    int c0 = blockIdx.x * 32, r0 = blockIdx.y * 32;
    #pragma unroll
    for (int i = 0; i < 4; i++) {
        t[ty + i * 8][tx] = W[(long)(r0 + ty + i * 8) * Ncols + c0 + tx];
    }
    __syncthreads();
    #pragma unroll
    for (int i = 0; i < 4; i++) {
        WT[(long)(c0 + ty + i * 8) * R + r0 + tx] = __float2bfloat16(t[tx][ty + i * 8]);
    }
}

// ---------------- bf16 GEMM: cp.async + ldmatrix pipeline ----------------
// C[M,N] = A[M,K] @ BT[N,K]^T (+ residual when EPI==1)
// 128x128 block tile, 256 threads / 8 warps (warp tile 32x64), K-tiles of 64
// (128-byte rows), 3-stage cp.async ring, SW swizzle chunk ^= (row&7) so
// cp.async stores and all ldmatrix reads are conflict-free. 2 CTAs/SM.
// smem: 3 stages x (A 16KB + B 16KB) = 96KB dynamic.
template<int EPI>
__global__ __launch_bounds__(256, 2) void gemm_cp(const __nv_bfloat16* __restrict__ A,
                                                  const __nv_bfloat16* __restrict__ B,
                                                  const float* __restrict__ Aux,
                                                  float* __restrict__ C,
                                                  int K, int N)
{
    extern __shared__ __align__(16) uint8_t dynsm[];
    const uint32_t sm0 = smem_to_u32(dynsm);
    const int tid = threadIdx.x;
    const int lane = tid & 31, warp = tid >> 5;
    const int col0 = blockIdx.x * 128;
    const long row0 = (long)blockIdx.y * 128;
    const int mW = (warp >> 1) * 32, nW = (warp & 1) * 64;
    const int gid = lane >> 2, tg = lane & 3;

    // staging role: threads 0-127 load A rows, 128-255 load B rows (one 128B row each)
    const int op = tid >> 7;
    const int s  = tid & 127;
    const __nv_bfloat16* grow =
        (op ? (B + (long)col0 * K) : (A + row0 * K)) + (long)s * K;
    const uint32_t dstrow = sm0 + op * 16384 + (uint32_t)s * 128;
    const int sw = s & 7;

    auto issue_stage = [&](int j) {
        uint32_t d = dstrow + (uint32_t)((j % 3) * 32768);
        const __nv_bfloat16* g = grow + j * 64;
        #pragma unroll
        for (int c = 0; c < 8; c++) {
            uint32_t da = d + (uint32_t)(((c ^ sw) & 7) * 16);
            asm volatile("cp.async.cg.shared.global [%0], [%1], 16;"
                :: "r"(da), "l"(g + c * 8) : "memory");
        }
    };

    float acc[2][8][4];
    #pragma unroll
    for (int mi = 0; mi < 2; mi++)
        #pragma unroll
        for (int ni = 0; ni < 8; ni++)
            #pragma unroll
            for (int j = 0; j < 4; j++) acc[mi][ni][j] = 0.f;

    const int KT = K >> 6;
    issue_stage(0);
    asm volatile("cp.async.commit_group;" ::: "memory");
    issue_stage(1);
    asm volatile("cp.async.commit_group;" ::: "memory");

    const int rA = lane & 15;        // row-within-16 for ldmatrix
    const int q  = lane >> 4;        // k8-chunk selector
    const uint32_t x7 = (uint32_t)(rA & 7);

    for (int kt = 0; kt < KT; kt++) {
        asm volatile("cp.async.wait_group 1;" ::: "memory");
        __syncthreads();
        const uint32_t st = (uint32_t)((kt % 3) * 32768);
        const uint32_t aBase = sm0 + st + (uint32_t)((mW + rA) * 128);
        const uint32_t bBase = sm0 + st + 16384u + (uint32_t)((nW + rA) * 128);
        #pragma unroll
        for (int ks = 0; ks < 4; ks++) {
            const uint32_t xo = ((((uint32_t)(2 * ks + q)) ^ x7) & 7) * 16;
            uint32_t a[2][4], b[8][2];
            LDSM_X4(a[0][0], a[0][1], a[0][2], a[0][3], aBase + xo);
            LDSM_X4(a[1][0], a[1][1], a[1][2], a[1][3], aBase + 2048 + xo);
            #pragma unroll
            for (int p = 0; p < 4; p++) {
                uint32_t t0, t1, t2, t3;
                LDSM_X4(t0, t1, t2, t3, bBase + (uint32_t)(p * 2048) + xo);
                b[2*p][0] = t0; b[2*p+1][0] = t1; b[2*p][1] = t2; b[2*p+1][1] = t3;
            }
            #pragma unroll
            for (int mi = 0; mi < 2; mi++)
                #pragma unroll
                for (int ni = 0; ni < 8; ni++)
                    mma_bf16(acc[mi][ni], a[mi], b[ni]);
        }
        if (kt + 2 < KT) issue_stage(kt + 2);
        asm volatile("cp.async.commit_group;" ::: "memory");
    }

    // epilogue: c0,c1 -> (row, 2tg..2tg+1); c2,c3 -> (row+8, same cols)
    #pragma unroll
    for (int mi = 0; mi < 2; mi++) {
        long r = row0 + mW + mi * 16 + gid;
        #pragma unroll
        for (int ni = 0; ni < 8; ni++) {
            long c = col0 + nW + ni * 8 + 2 * tg;
            float2 v0 = make_float2(acc[mi][ni][0], acc[mi][ni][1]);
            float2 v1 = make_float2(acc[mi][ni][2], acc[mi][ni][3]);
            if (EPI == 1) {
                float2 r0 = *(const float2*)(Aux + r * N + c);
                float2 r1 = *(const float2*)(Aux + (r + 8) * N + c);
                v0.x += r0.x; v0.y += r0.y; v1.x += r1.x; v1.y += r1.y;
            }
            *(float2*)(C + r * N + c)       = v0;
            *(float2*)(C + (r + 8) * N + c) = v1;
        }
    }
}

// ---------------- depthwise causal conv (K=4) + bias + silu ----------------
__global__ __launch_bounds__(256) void conv_kernel(const float* __restrict__ xr,
                                                   const float* __restrict__ cw,
                                                   const float* __restrict__ cb,
                                                   float* __restrict__ u)
{
    int idx = blockIdx.x * 256 + threadIdx.x;
    int d   = idx & (DINNER - 1);
    int tok = idx >> 11;
    int t   = tok & (NT - 1);
    const float* p = xr + (size_t)tok * (2*DINNER) + d;
    float w0 = cw[d*4+0], w1 = cw[d*4+1], w2 = cw[d*4+2], w3 = cw[d*4+3];
    float acc = cb[d] + w3 * p[0];
    if (t >= 1) acc = fmaf(w2, p[-(2*DINNER)],   acc);
    if (t >= 2) acc = fmaf(w1, p[-2*(2*DINNER)], acc);
    if (t >= 3) acc = fmaf(w0, p[-3*(2*DINNER)], acc);
    u[idx] = acc / (1.0f + __expf(-acc));
}

// ---------------- tf32 mma.sync GEMM (dt path: K=64, bias+softplus epilogue) ----------------
__global__ __launch_bounds__(256) void gemm_dt_tc(const float* __restrict__ A,
                                                  const float* __restrict__ B,
                                                  const float* __restrict__ Aux,
                                                  float* __restrict__ C,
                                                  int K, int N, int lda)
{
    __shared__ float As[2][16][136];
    __shared__ float Bs[2][16][136];
    const int tid = threadIdx.x;
    const int col0 = blockIdx.x * 128;
    const long row0 = (long)blockIdx.y * 128;
    const int lane = tid & 31, warp = tid >> 5;
    const int mW = (warp >> 1) * 32, nW = (warp & 1) * 64;
    const int gid = lane >> 2, tg = lane & 3;

    const int arow = tid >> 2;
    const int acg  = tid & 3;
    const float* Ap = A + (row0 + arow) * (long)lda + acg * 4;
    const int bk  = tid >> 5;
    const int bn4 = tid & 31;
    const float* Bp = B + (long)bk * N + col0 + bn4 * 4;

    float4 pa[2], pb[2];
    pa[0] = *(const float4*)(Ap);
    pa[1] = *(const float4*)(Ap + 64 * (long)lda);
    pb[0] = *(const float4*)(Bp);
    pb[1] = *(const float4*)(Bp + 8 * (long)N);

    float acc[2][8][4];
    #pragma unroll
    for (int mi = 0; mi < 2; mi++)
        #pragma unroll
        for (int ni = 0; ni < 8; ni++)
            #pragma unroll
            for (int j = 0; j < 4; j++) acc[mi][ni][j] = 0.f;

    const int KT = K >> 4;
    int buf = 0;
    #pragma unroll
    for (int i = 0; i < 2; i++) {
        int rr = arow + i * 64;
        float v[4] = {pa[i].x, pa[i].y, pa[i].z, pa[i].w};
        #pragma unroll
        for (int j = 0; j < 4; j++) {
            int c = acg * 4 + j;
            As[0][c][rr ^ (((c >> 2) & 3) << 3)] = to_tf32(v[j]);
        }
        float4 qv = pb[i];
        qv.x = to_tf32(qv.x); qv.y = to_tf32(qv.y);
        qv.z = to_tf32(qv.z); qv.w = to_tf32(qv.w);
        *(float4*)&Bs[0][bk + i * 8][bn4 * 4] = qv;
    }
    __syncthreads();

    for (int kt = 0; kt < KT; kt++) {
        if (kt + 1 < KT) {
            pa[0] = *(const float4*)(Ap + (kt + 1) * 16);
            pa[1] = *(const float4*)(Ap + (kt + 1) * 16 + 64 * (long)lda);
            pb[0] = *(const float4*)(Bp + (long)((kt + 1) * 16) * N);
            pb[1] = *(const float4*)(Bp + (long)((kt + 1) * 16 + 8) * N);
        }
        #pragma unroll
        for (int ks = 0; ks < 2; ks++) {
            const int k0 = ks * 8;
            const int kA = k0 + tg, kB = k0 + tg + 4;
            const int sA = ((kA >> 2) & 3) << 3;
            const int sB = ((kB >> 2) & 3) << 3;
            float a[2][4], b[8][2];
            #pragma unroll
            for (int mi = 0; mi < 2; mi++) {
                int m = mW + mi * 16 + gid;
                a[mi][0] = As[buf][kA][m ^ sA];
                a[mi][1] = As[buf][kA][(m + 8) ^ sA];
                a[mi][2] = As[buf][kB][m ^ sB];
                a[mi][3] = As[buf][kB][(m + 8) ^ sB];
            }
            #pragma unroll
            for (int ni = 0; ni < 8; ni++) {
                int n = nW + ni * 8 + gid;
                b[ni][0] = Bs[buf][kA][n];
                b[ni][1] = Bs[buf][kB][n];
            }
            #pragma unroll
            for (int mi = 0; mi < 2; mi++)
                #pragma unroll
                for (int ni = 0; ni < 8; ni++)
                    mma_tf32(acc[mi][ni], a[mi], b[ni]);
        }
        if (kt + 1 < KT) {
            int nb = buf ^ 1;
            #pragma unroll
            for (int i = 0; i < 2; i++) {
                int rr = arow + i * 64;
                float v[4] = {pa[i].x, pa[i].y, pa[i].z, pa[i].w};
                #pragma unroll
                for (int j = 0; j < 4; j++) {
                    int c = acg * 4 + j;
                    As[nb][c][rr ^ (((c >> 2) & 3) << 3)] = to_tf32(v[j]);
                }
                float4 qv = pb[i];
                qv.x = to_tf32(qv.x); qv.y = to_tf32(qv.y);
                qv.z = to_tf32(qv.z); qv.w = to_tf32(qv.w);
                *(float4*)&Bs[nb][bk + i * 8][bn4 * 4] = qv;
            }
            __syncthreads();
            buf = nb;
        }
    }

    #pragma unroll
    for (int mi = 0; mi < 2; mi++) {
        long rr = row0 + mW + mi * 16 + gid;
        #pragma unroll
        for (int ni = 0; ni < 8; ni++) {
            long c = col0 + nW + ni * 8 + 2 * tg;
            float2 v0 = make_float2(acc[mi][ni][0], acc[mi][ni][1]);
            float2 v1 = make_float2(acc[mi][ni][2], acc[mi][ni][3]);
            float b0 = Aux[c], b1 = Aux[c + 1];
            v0.x = softplusf(v0.x + b0); v0.y = softplusf(v0.y + b1);
            v1.x = softplusf(v1.x + b0); v1.y = softplusf(v1.y + b1);
            *(float2*)(C + rr * N + c)       = v0;
            *(float2*)(C + (rr + 8) * N + c) = v1;
        }
    }
}

// ---------------- gemm_wx: tf32 split-K tensor GEMM ----------------
__global__ __launch_bounds__(128) void gemm_wx_tc(const float* __restrict__ A,
                                                  const float* __restrict__ W,
                                                  float* __restrict__ P)
{
    __shared__ float As[2][16][136];
    __shared__ float Ws[2][16][104];
    const int tid = threadIdx.x;
    const long row0 = (long)blockIdx.x * 128;
    const int kblk = blockIdx.y;
    const int lane = tid & 31, warp = tid >> 5;
    const int mW = (warp >> 1) * 64, nW = (warp & 1) * 48;
    const int gid = lane >> 2, tg = lane & 3;

    const int arow = tid >> 2;
    const int acg  = tid & 3;
    const float* Ap = A + (row0 + arow) * (long)DINNER + kblk * 256 + acg * 4;
    int wr[3], wc[3];
    #pragma unroll
    for (int i = 0; i < 3; i++) {
        int idx = tid + i * 128;
        wr[i] = idx / 24; wc[i] = idx - wr[i] * 24;
    }
    const float* Wp = W + (long)(kblk * 256) * XDBC;

    float4 pa[4], pw[3];
    #pragma unroll
    for (int i = 0; i < 4; i++) pa[i] = *(const float4*)(Ap + (long)i * 32 * DINNER);
    #pragma unroll
    for (int i = 0; i < 3; i++) pw[i] = *(const float4*)(Wp + (long)wr[i] * XDBC + wc[i] * 4);

    float acc[4][6][4];
    #pragma unroll
    for (int mi = 0; mi < 4; mi++)
        #pragma unroll
        for (int ni = 0; ni < 6; ni++)
            #pragma unroll
            for (int j = 0; j < 4; j++) acc[mi][ni][j] = 0.f;

    int buf = 0;
    #pragma unroll
    for (int i = 0; i < 4; i++) {
        int rr = arow + i * 32;
        float v[4] = {pa[i].x, pa[i].y, pa[i].z, pa[i].w};
        #pragma unroll
        for (int j = 0; j < 4; j++) {
            int c = acg * 4 + j;
            As[0][c][rr ^ (((c >> 2) & 3) << 3)] = to_tf32(v[j]);
        }
    }
    #pragma unroll
    for (int i = 0; i < 3; i++) {
        float4 qv = pw[i];
        qv.x = to_tf32(qv.x); qv.y = to_tf32(qv.y);
        qv.z = to_tf32(qv.z); qv.w = to_tf32(qv.w);
        *(float4*)&Ws[0][wr[i]][wc[i] * 4] = qv;
    }
    __syncthreads();

    const int KT = 256 / 16;
    for (int kt = 0; kt < KT; kt++) {
        if (kt + 1 < KT) {
            #pragma unroll
            for (int i = 0; i < 4; i++)
                pa[i] = *(const float4*)(Ap + (kt + 1) * 16 + (long)i * 32 * DINNER);
            #pragma unroll
            for (int i = 0; i < 3; i++)
                pw[i] = *(const float4*)(Wp + (long)((kt + 1) * 16 + wr[i]) * XDBC + wc[i] * 4);
        }
        #pragma unroll
        for (int ks = 0; ks < 2; ks++) {
            const int k0 = ks * 8;
            const int kA = k0 + tg, kB = k0 + tg + 4;
            const int sA = ((kA >> 2) & 3) << 3;
            const int sB = ((kB >> 2) & 3) << 3;
            float a[4][4], b[6][2];
            #pragma unroll
            for (int mi = 0; mi < 4; mi++) {
                int m = mW + mi * 16 + gid;
                a[mi][0] = As[buf][kA][m ^ sA];
                a[mi][1] = As[buf][kA][(m + 8) ^ sA];
                a[mi][2] = As[buf][kB][m ^ sB];
                a[mi][3] = As[buf][kB][(m + 8) ^ sB];
            }
            #pragma unroll
            for (int ni = 0; ni < 6; ni++) {
                int n = nW + ni * 8 + gid;
                b[ni][0] = Ws[buf][kA][n];
                b[ni][1] = Ws[buf][kB][n];
            }
            #pragma unroll
            for (int mi = 0; mi < 4; mi++)
                #pragma unroll
                for (int ni = 0; ni < 6; ni++)
                    mma_tf32(acc[mi][ni], a[mi], b[ni]);
        }
        if (kt + 1 < KT) {
            int nb = buf ^ 1;
            #pragma unroll
            for (int i = 0; i < 4; i++) {
                int rr = arow + i * 32;
                float v[4] = {pa[i].x, pa[i].y, pa[i].z, pa[i].w};
                #pragma unroll
                for (int j = 0; j < 4; j++) {
                    int c = acg * 4 + j;
                    As[nb][c][rr ^ (((c >> 2) & 3) << 3)] = to_tf32(v[j]);
                }
            }
            #pragma unroll
            for (int i = 0; i < 3; i++) {
                float4 qv = pw[i];
                qv.x = to_tf32(qv.x); qv.y = to_tf32(qv.y);
                qv.z = to_tf32(qv.z); qv.w = to_tf32(qv.w);
                *(float4*)&Ws[nb][wr[i]][wc[i] * 4] = qv;
            }
            __syncthreads();
            buf = nb;
        }
    }

    float* Pb = P + (size_t)kblk * NTOK * XDBC;
    #pragma unroll
    for (int mi = 0; mi < 4; mi++) {
        long rr = row0 + mW + mi * 16 + gid;
        #pragma unroll
        for (int ni = 0; ni < 6; ni++) {
            long c = nW + ni * 8 + 2 * tg;
            *(float2*)(Pb + rr * XDBC + c)       = make_float2(acc[mi][ni][0], acc[mi][ni][1]);
            *(float2*)(Pb + (rr + 8) * XDBC + c) = make_float2(acc[mi][ni][2], acc[mi][ni][3]);
        }
    }
}

__global__ __launch_bounds__(256) void wx_reduce(const float* __restrict__ P,
                                                 float* __restrict__ C)
{
    size_t i = (size_t)blockIdx.x * 256 + threadIdx.x;
    const float4* p = (const float4*)P;
    const size_t stride = (size_t)NTOK * XDBC / 4;
    float4 s = p[i];
    #pragma unroll
    for (int k = 1; k < WX_SPLIT; k++) {
        float4 t = p[i + (size_t)k * stride];
        s.x += t.x; s.y += t.y; s.z += t.z; s.w += t.w;
    }
    ((float4*)C)[i] = s;
}

// ---------------- selective scan (bf16 y output) ----------------
__global__ __launch_bounds__(128) void scan_kernel(const float* __restrict__ delta,
                                                   const float* __restrict__ u,
                                                   const float* __restrict__ xdbc,
                                                   const float* __restrict__ xr,
                                                   const float* __restrict__ A_log,
                                                   const float* __restrict__ Dp,
                                                   __nv_bfloat16* __restrict__ y)
{
    __shared__ float sd[64][8], su[64][8], sres[64][8], ybuf[64][8];
    __shared__ float sbc[64][32];
    __shared__ float sD[8];

    int b     = blockIdx.x >> 8;
    int dbase = (blockIdx.x & 255) * 8;
    int tid   = threadIdx.x;
    int lane  = tid & 31, w = tid >> 5;
    int dloc  = 2 * w + (lane >> 4);
    int n     = lane & 15;
    int d     = dbase + dloc;

    float Ac = -expf(A_log[d * DSTATE + n]);
    if (tid < 8) sD[tid] = Dp[dbase + tid];

    float h = 0.0f;
    long tokbase = (long)b * NT;

    for (int c = 0; c < NT / 64; c++) {
        int t0 = c * 64;
        for (int i = tid; i < 512; i += 128) {
            int tl = i >> 3, dl = i & 7;
            long g = (tokbase + t0 + tl) * (long)DINNER + dbase + dl;
            sd[tl][dl]   = delta[g];
            su[tl][dl]   = u[g];
            sres[tl][dl] = xr[(tokbase + t0 + tl) * (long)(2*DINNER) + DINNER + dbase + dl];
        }
        for (int i = tid; i < 2048; i += 128) {
            int tl = i >> 5, cc = i & 31;
            sbc[tl][cc] = xdbc[(tokbase + t0 + tl) * (long)XDBC + DTRANK + cc];
        }
        __syncthreads();

        #pragma unroll 4
        for (int tl = 0; tl < 64; tl++) {
            float dlt = sd[tl][dloc];
            float uu  = su[tl][dloc];
            float a   = __expf(dlt * Ac);
            h = fmaf(a, h, dlt * uu * sbc[tl][n]);
            float p = h * sbc[tl][16 + n];
            p += __shfl_xor_sync(0xffffffffu, p, 8);
            p += __shfl_xor_sync(0xffffffffu, p, 4);
            p += __shfl_xor_sync(0xffffffffu, p, 2);
            p += __shfl_xor_sync(0xffffffffu, p, 1);
            if (n == 0) ybuf[tl][dloc] = p;
        }
        __syncthreads();

        for (int i = tid; i < 512; i += 128) {
            int tl = i >> 3, dl = i & 7;
            float uu = su[tl][dl];
            float r  = sres[tl][dl];
            float yy = (ybuf[tl][dl] + uu * sD[dl]) * (r / (1.0f + __expf(-r)));
            y[(tokbase + t0 + tl) * (long)DINNER + dbase + dl] = __float2bfloat16(yy);
        }
        __syncthreads();
    }
}

// ---------------- launch ----------------
extern "C" void kernel_launch(void* const* d_in, const int* in_sizes, int n_in,
                              void* d_out, int out_size)
{
    (void)in_sizes; (void)n_in; (void)out_size;
    const float* x      = (const float*)d_in[0];
    const float* norm_w = (const float*)d_in[1];
    const float* w_in   = (const float*)d_in[2];
    const float* conv_w = (const float*)d_in[3];
    const float* conv_b = (const float*)d_in[4];
    const float* w_x    = (const float*)d_in[5];
    const float* w_dt   = (const float*)d_in[6];
    const float* b_dt   = (const float*)d_in[7];
    const float* A_log  = (const float*)d_in[8];
    const float* Dp     = (const float*)d_in[9];
    const float* w_out  = (const float*)d_in[10];
    float* out = (float*)d_out;

    __nv_bfloat16* p_xnbf  = 0;
    __nv_bfloat16* p_ybf   = 0;
    __nv_bfloat16* p_winT  = 0;
    __nv_bfloat16* p_woutT = 0;
    float* p_xr    = 0;
    float* p_u     = 0;
    float* p_xdbc  = 0;
    float* p_delta = 0;
    float* p_part  = 0;
    cudaGetSymbolAddress((void**)&p_xnbf,  g_xn_bf);
    cudaGetSymbolAddress((void**)&p_xr,    g_xr);
    cudaGetSymbolAddress((void**)&p_u,     g_u);
    cudaGetSymbolAddress((void**)&p_xdbc,  g_xdbc);
    cudaGetSymbolAddress((void**)&p_delta, g_delta);
    cudaGetSymbolAddress((void**)&p_ybf,   g_y_bf);
    cudaGetSymbolAddress((void**)&p_part,  g_part);
    cudaGetSymbolAddress((void**)&p_winT,  g_winT);
    cudaGetSymbolAddress((void**)&p_woutT, g_woutT);

    const int SMEM_GEMM = 3 * 32768;   // 96KB dynamic
    cudaFuncSetAttribute(gemm_cp<0>, cudaFuncAttributeMaxDynamicSharedMemorySize, SMEM_GEMM);
    cudaFuncSetAttribute(gemm_cp<1>, cudaFuncAttributeMaxDynamicSharedMemorySize, SMEM_GEMM);

    // 1. rmsnorm -> bf16 xn
    rms_kernel<<<NTOK, 256>>>(x, norm_w, p_xnbf);
    // 1b. weight transposes -> bf16 [N][K]
    transpose_bf<<<dim3((2*DINNER)/32, DMODEL/32), 256>>>(w_in, p_winT, DMODEL, 2*DINNER);
    transpose_bf<<<dim3(DMODEL/32, DINNER/32), 256>>>(w_out, p_woutT, DINNER, DMODEL);
    // 2. xr = xn @ w_in   [bf16 cp.async + ldmatrix]
    gemm_cp<0><<<dim3((2*DINNER)/128, NTOK/128), 256, SMEM_GEMM>>>(
        p_xnbf, p_winT, (const float*)0, p_xr, DMODEL, 2*DINNER);
    // 3. u = silu(depthwise_conv(xr[:, :2048]) + conv_b)
    conv_kernel<<<(NTOK*DINNER)/256, 256>>>(p_xr, conv_w, conv_b, p_u);
    // 4. xdbc = u @ w_x   [tf32 split-K + reduce]
    gemm_wx_tc<<<dim3(NTOK/128, WX_SPLIT), 128>>>(p_u, w_x, p_part);
    wx_reduce<<<(NTOK*XDBC/4)/256, 256>>>(p_part, p_xdbc);
    // 5. delta = softplus(dt @ w_dt + b_dt)   [tf32 mma, K=64]
    gemm_dt_tc<<<dim3(DINNER/128, NTOK/128), 256>>>(p_xdbc, w_dt, b_dt, p_delta, DTRANK, DINNER, XDBC);
    // 6. selective scan + gating -> bf16 y
    scan_kernel<<<NB*256, 128>>>(p_delta, p_u, p_xdbc, p_xr, A_log, Dp, p_ybf);
    // 7. out = y @ w_out + x   [bf16 cp.async + ldmatrix + residual]
    gemm_cp<1><<<dim3(DMODEL/128, NTOK/128), 256, SMEM_GEMM>>>(
        p_ybf, p_woutT, x, out, DINNER, DMODEL);
}

// round 17
// speedup vs baseline: 1.5852x; 1.0489x over previous
#include <cuda_runtime.h>
#include <cuda_bf16.h>
#include <math.h>
#include <stdint.h>

// ---------------- problem constants ----------------
#define DMODEL 1024
#define DINNER 2048
#define DSTATE 16
#define DTRANK 64
#define XDBC   96        // DTRANK + 2*DSTATE
#define NB     2
#define NT     4096
#define NTOK   (NB*NT)   // 8192
#define EPSRMS 1e-5f
#define WX_SPLIT 8

// ---------------- scratch (static device globals; no runtime alloc) ----------------
__device__ __align__(16) __nv_bfloat16 g_xn_bf[(size_t)NTOK * DMODEL];
__device__ float g_xr[(size_t)NTOK * 2 * DINNER];      // (u_raw | res)
__device__ float g_u [(size_t)NTOK * DINNER];
__device__ float g_xdbc[(size_t)NTOK * XDBC];          // (dt | B | C)
__device__ float g_delta[(size_t)NTOK * DINNER];
__device__ __align__(16) __nv_bfloat16 g_y_bf[(size_t)NTOK * DINNER];
__device__ float g_part[(size_t)WX_SPLIT * NTOK * XDBC];
__device__ __align__(16) __nv_bfloat16 g_winT[(size_t)(2*DINNER) * DMODEL];   // [4096][1024]
__device__ __align__(16) __nv_bfloat16 g_woutT[(size_t)DMODEL * DINNER];      // [1024][2048]

// ---------------- helpers ----------------
__device__ __forceinline__ uint32_t smem_to_u32(const void* smem_ptr) {
    uint32_t addr;
    asm("{ .reg .u64 tmp; cvta.to.shared.u64 tmp, %1; cvt.u32.u64 %0, tmp; }"
        : "=r"(addr) : "l"(smem_ptr));
    return addr;
}
__device__ __forceinline__ float to_tf32(float x) {
    float r;
    asm("cvt.rna.tf32.f32 %0, %1;" : "=f"(r) : "f"(x));
    return r;
}
__device__ __forceinline__ void mma_tf32(float* c, const float* a, const float* b) {
    asm volatile(
        "mma.sync.aligned.m16n8k8.row.col.f32.tf32.tf32.f32 "
        "{%0,%1,%2,%3}, {%4,%5,%6,%7}, {%8,%9}, {%0,%1,%2,%3};\n"
        : "+f"(c[0]), "+f"(c[1]), "+f"(c[2]), "+f"(c[3])
        : "r"(__float_as_uint(a[0])), "r"(__float_as_uint(a[1])),
          "r"(__float_as_uint(a[2])), "r"(__float_as_uint(a[3])),
          "r"(__float_as_uint(b[0])), "r"(__float_as_uint(b[1])));
}
__device__ __forceinline__ void mma_bf16(float* c, const uint32_t* a, const uint32_t* b) {
    asm volatile(
        "mma.sync.aligned.m16n8k16.row.col.f32.bf16.bf16.f32 "
        "{%0,%1,%2,%3}, {%4,%5,%6,%7}, {%8,%9}, {%0,%1,%2,%3};\n"
        : "+f"(c[0]), "+f"(c[1]), "+f"(c[2]), "+f"(c[3])
        : "r"(a[0]), "r"(a[1]), "r"(a[2]), "r"(a[3]),
          "r"(b[0]), "r"(b[1]));
}
#define LDSM_X4(r0, r1, r2, r3, addr) \
    asm volatile("ldmatrix.sync.aligned.m8n8.x4.shared.b16 {%0,%1,%2,%3}, [%4];" \
        : "=r"(r0), "=r"(r1), "=r"(r2), "=r"(r3) : "r"(addr))

__device__ __forceinline__ float softplusf(float v) {
    return (v > 20.0f) ? v : log1pf(expf(v));
}

// ---------------- rmsnorm: one block per token, bf16 output ----------------
__global__ __launch_bounds__(256) void rms_kernel(const float* __restrict__ x,
                                                  const float* __restrict__ w,
                                                  __nv_bfloat16* __restrict__ xn)
{
    int row = blockIdx.x;
    const float4* xin = (const float4*)(x + (size_t)row * DMODEL);
    float4 v = xin[threadIdx.x];
    float ss = v.x*v.x + v.y*v.y + v.z*v.z + v.w*v.w;
    #pragma unroll
    for (int o = 16; o; o >>= 1) ss += __shfl_xor_sync(0xffffffffu, ss, o);
    __shared__ float sred[8];
    if ((threadIdx.x & 31) == 0) sred[threadIdx.x >> 5] = ss;
    __syncthreads();
    if (threadIdx.x < 8) {
        float t = sred[threadIdx.x];
        #pragma unroll
        for (int o = 4; o; o >>= 1) t += __shfl_xor_sync(0xffu, t, o);
        if (threadIdx.x == 0) sred[0] = t;
    }
    __syncthreads();
    float scale = rsqrtf(sred[0] * (1.0f / DMODEL) + EPSRMS);
    float4 wv = ((const float4*)w)[threadIdx.x];
    __nv_bfloat162 b0, b1;
    b0.x = __float2bfloat16(v.x * scale * wv.x);
    b0.y = __float2bfloat16(v.y * scale * wv.y);
    b1.x = __float2bfloat16(v.z * scale * wv.z);
    b1.y = __float2bfloat16(v.w * scale * wv.w);
    __nv_bfloat162* po = (__nv_bfloat162*)(xn + (size_t)row * DMODEL);
    po[2 * threadIdx.x]     = b0;
    po[2 * threadIdx.x + 1] = b1;
}

// ---------------- transpose + fp32->bf16: W[R][Ncols] -> WT[Ncols][R] ----------------
__global__ __launch_bounds__(256) void transpose_bf(const float* __restrict__ W,
                                                    __nv_bfloat16* __restrict__ WT,
                                                    int R, int Ncols)
{
    __shared__ float t[32][33];
    int tx = threadIdx.x & 31, ty = threadIdx.x >> 5;
    int c0 = blockIdx.x * 32, r0 = blockIdx.y * 32;
    #pragma unroll
    for (int i = 0; i < 4; i++) {
        t[ty + i * 8][tx] = W[(long)(r0 + ty + i * 8) * Ncols + c0 + tx];
    }
    __syncthreads();
    #pragma unroll
    for (int i = 0; i < 4; i++) {
        WT[(long)(c0 + ty + i * 8) * R + r0 + tx] = __float2bfloat16(t[tx][ty + i * 8]);
    }
}

// ---------------- bf16 GEMM: cp.async + ldmatrix pipeline ----------------
// C[M,N] = A[M,K] @ BT[N,K]^T (+ residual when EPI==1)
// 128x128 block tile, 256 threads / 8 warps (warp tile 32x64), K-tiles of 64,
// 3-stage cp.async ring with EARLY prefetch issue (issued before compute so the
// awaited group ages ~2 tile-computes before its wait). 2 CTAs/SM, 96KB dynamic.
template<int EPI>
__global__ __launch_bounds__(256, 2) void gemm_cp(const __nv_bfloat16* __restrict__ A,
                                                  const __nv_bfloat16* __restrict__ B,
                                                  const float* __restrict__ Aux,
                                                  float* __restrict__ C,
                                                  int K, int N)
{
    extern __shared__ __align__(16) uint8_t dynsm[];
    const uint32_t sm0 = smem_to_u32(dynsm);
    const int tid = threadIdx.x;
    const int lane = tid & 31, warp = tid >> 5;
    const int col0 = blockIdx.x * 128;
    const long row0 = (long)blockIdx.y * 128;
    const int mW = (warp >> 1) * 32, nW = (warp & 1) * 64;
    const int gid = lane >> 2, tg = lane & 3;

    const int op = tid >> 7;
    const int s  = tid & 127;
    const __nv_bfloat16* grow =
        (op ? (B + (long)col0 * K) : (A + row0 * K)) + (long)s * K;
    const uint32_t dstrow = sm0 + op * 16384 + (uint32_t)s * 128;
    const int sw = s & 7;

    auto issue_stage = [&](int j) {
        uint32_t d = dstrow + (uint32_t)((j % 3) * 32768);
        const __nv_bfloat16* g = grow + j * 64;
        #pragma unroll
        for (int c = 0; c < 8; c++) {
            uint32_t da = d + (uint32_t)(((c ^ sw) & 7) * 16);
            asm volatile("cp.async.cg.shared.global [%0], [%1], 16;"
                :: "r"(da), "l"(g + c * 8) : "memory");
        }
    };

    float acc[2][8][4];
    #pragma unroll
    for (int mi = 0; mi < 2; mi++)
        #pragma unroll
        for (int ni = 0; ni < 8; ni++)
            #pragma unroll
            for (int j = 0; j < 4; j++) acc[mi][ni][j] = 0.f;

    const int KT = K >> 6;
    issue_stage(0);
    asm volatile("cp.async.commit_group;" ::: "memory");
    issue_stage(1);
    asm volatile("cp.async.commit_group;" ::: "memory");

    const int rA = lane & 15;
    const int q  = lane >> 4;
    const uint32_t x7 = (uint32_t)(rA & 7);

    for (int kt = 0; kt < KT; kt++) {
        asm volatile("cp.async.wait_group 1;" ::: "memory");
        __syncthreads();
        // EARLY prefetch: buffer (kt+2)%3 == (kt-1)%3, fully consumed before the sync
        if (kt + 2 < KT) issue_stage(kt + 2);
        asm volatile("cp.async.commit_group;" ::: "memory");
        const uint32_t st = (uint32_t)((kt % 3) * 32768);
        const uint32_t aBase = sm0 + st + (uint32_t)((mW + rA) * 128);
        const uint32_t bBase = sm0 + st + 16384u + (uint32_t)((nW + rA) * 128);
        #pragma unroll
        for (int ks = 0; ks < 4; ks++) {
            const uint32_t xo = ((((uint32_t)(2 * ks + q)) ^ x7) & 7) * 16;
            uint32_t a[2][4], b[8][2];
            LDSM_X4(a[0][0], a[0][1], a[0][2], a[0][3], aBase + xo);
            LDSM_X4(a[1][0], a[1][1], a[1][2], a[1][3], aBase + 2048 + xo);
            #pragma unroll
            for (int p = 0; p < 4; p++) {
                uint32_t t0, t1, t2, t3;
                LDSM_X4(t0, t1, t2, t3, bBase + (uint32_t)(p * 2048) + xo);
                b[2*p][0] = t0; b[2*p+1][0] = t1; b[2*p][1] = t2; b[2*p+1][1] = t3;
            }
            #pragma unroll
            for (int mi = 0; mi < 2; mi++)
                #pragma unroll
                for (int ni = 0; ni < 8; ni++)
                    mma_bf16(acc[mi][ni], a[mi], b[ni]);
        }
    }

    #pragma unroll
    for (int mi = 0; mi < 2; mi++) {
        long r = row0 + mW + mi * 16 + gid;
        #pragma unroll
        for (int ni = 0; ni < 8; ni++) {
            long c = col0 + nW + ni * 8 + 2 * tg;
            float2 v0 = make_float2(acc[mi][ni][0], acc[mi][ni][1]);
            float2 v1 = make_float2(acc[mi][ni][2], acc[mi][ni][3]);
            if (EPI == 1) {
                float2 r0 = *(const float2*)(Aux + r * N + c);
                float2 r1 = *(const float2*)(Aux + (r + 8) * N + c);
                v0.x += r0.x; v0.y += r0.y; v1.x += r1.x; v1.y += r1.y;
            }
            *(float2*)(C + r * N + c)       = v0;
            *(float2*)(C + (r + 8) * N + c) = v1;
        }
    }
}

// ---------------- depthwise causal conv (K=4) + bias + silu ----------------
__global__ __launch_bounds__(256) void conv_kernel(const float* __restrict__ xr,
                                                   const float* __restrict__ cw,
                                                   const float* __restrict__ cb,
                                                   float* __restrict__ u)
{
    int idx = blockIdx.x * 256 + threadIdx.x;
    int d   = idx & (DINNER - 1);
    int tok = idx >> 11;
    int t   = tok & (NT - 1);
    const float* p = xr + (size_t)tok * (2*DINNER) + d;
    float w0 = cw[d*4+0], w1 = cw[d*4+1], w2 = cw[d*4+2], w3 = cw[d*4+3];
    float acc = cb[d] + w3 * p[0];
    if (t >= 1) acc = fmaf(w2, p[-(2*DINNER)],   acc);
    if (t >= 2) acc = fmaf(w1, p[-2*(2*DINNER)], acc);
    if (t >= 3) acc = fmaf(w0, p[-3*(2*DINNER)], acc);
    u[idx] = acc / (1.0f + __expf(-acc));
}

// ---------------- tf32 mma.sync GEMM (dt path: K=64, bias+softplus epilogue) ----------------
__global__ __launch_bounds__(256) void gemm_dt_tc(const float* __restrict__ A,
                                                  const float* __restrict__ B,
                                                  const float* __restrict__ Aux,
                                                  float* __restrict__ C,
                                                  int K, int N, int lda)
{
    __shared__ float As[2][16][136];
    __shared__ float Bs[2][16][136];
    const int tid = threadIdx.x;
    const int col0 = blockIdx.x * 128;
    const long row0 = (long)blockIdx.y * 128;
    const int lane = tid & 31, warp = tid >> 5;
    const int mW = (warp >> 1) * 32, nW = (warp & 1) * 64;
    const int gid = lane >> 2, tg = lane & 3;

    const int arow = tid >> 2;
    const int acg  = tid & 3;
    const float* Ap = A + (row0 + arow) * (long)lda + acg * 4;
    const int bk  = tid >> 5;
    const int bn4 = tid & 31;
    const float* Bp = B + (long)bk * N + col0 + bn4 * 4;

    float4 pa[2], pb[2];
    pa[0] = *(const float4*)(Ap);
    pa[1] = *(const float4*)(Ap + 64 * (long)lda);
    pb[0] = *(const float4*)(Bp);
    pb[1] = *(const float4*)(Bp + 8 * (long)N);

    float acc[2][8][4];
    #pragma unroll
    for (int mi = 0; mi < 2; mi++)
        #pragma unroll
        for (int ni = 0; ni < 8; ni++)
            #pragma unroll
            for (int j = 0; j < 4; j++) acc[mi][ni][j] = 0.f;

    const int KT = K >> 4;
    int buf = 0;
    #pragma unroll
    for (int i = 0; i < 2; i++) {
        int rr = arow + i * 64;
        float v[4] = {pa[i].x, pa[i].y, pa[i].z, pa[i].w};
        #pragma unroll
        for (int j = 0; j < 4; j++) {
            int c = acg * 4 + j;
            As[0][c][rr ^ (((c >> 2) & 3) << 3)] = to_tf32(v[j]);
        }
        float4 qv = pb[i];
        qv.x = to_tf32(qv.x); qv.y = to_tf32(qv.y);
        qv.z = to_tf32(qv.z); qv.w = to_tf32(qv.w);
        *(float4*)&Bs[0][bk + i * 8][bn4 * 4] = qv;
    }
    __syncthreads();

    for (int kt = 0; kt < KT; kt++) {
        if (kt + 1 < KT) {
            pa[0] = *(const float4*)(Ap + (kt + 1) * 16);
            pa[1] = *(const float4*)(Ap + (kt + 1) * 16 + 64 * (long)lda);
            pb[0] = *(const float4*)(Bp + (long)((kt + 1) * 16) * N);
            pb[1] = *(const float4*)(Bp + (long)((kt + 1) * 16 + 8) * N);
        }
        #pragma unroll
        for (int ks = 0; ks < 2; ks++) {
            const int k0 = ks * 8;
            const int kA = k0 + tg, kB = k0 + tg + 4;
            const int sA = ((kA >> 2) & 3) << 3;
            const int sB = ((kB >> 2) & 3) << 3;
            float a[2][4], b[8][2];
            #pragma unroll
            for (int mi = 0; mi < 2; mi++) {
                int m = mW + mi * 16 + gid;
                a[mi][0] = As[buf][kA][m ^ sA];
                a[mi][1] = As[buf][kA][(m + 8) ^ sA];
                a[mi][2] = As[buf][kB][m ^ sB];
                a[mi][3] = As[buf][kB][(m + 8) ^ sB];
            }
            #pragma unroll
            for (int ni = 0; ni < 8; ni++) {
                int n = nW + ni * 8 + gid;
                b[ni][0] = Bs[buf][kA][n];
                b[ni][1] = Bs[buf][kB][n];
            }
            #pragma unroll
            for (int mi = 0; mi < 2; mi++)
                #pragma unroll
                for (int ni = 0; ni < 8; ni++)
                    mma_tf32(acc[mi][ni], a[mi], b[ni]);
        }
        if (kt + 1 < KT) {
            int nb = buf ^ 1;
            #pragma unroll
            for (int i = 0; i < 2; i++) {
                int rr = arow + i * 64;
                float v[4] = {pa[i].x, pa[i].y, pa[i].z, pa[i].w};
                #pragma unroll
                for (int j = 0; j < 4; j++) {
                    int c = acg * 4 + j;
                    As[nb][c][rr ^ (((c >> 2) & 3) << 3)] = to_tf32(v[j]);
                }
                float4 qv = pb[i];
                qv.x = to_tf32(qv.x); qv.y = to_tf32(qv.y);
                qv.z = to_tf32(qv.z); qv.w = to_tf32(qv.w);
                *(float4*)&Bs[nb][bk + i * 8][bn4 * 4] = qv;
            }
            __syncthreads();
            buf = nb;
        }
    }

    #pragma unroll
    for (int mi = 0; mi < 2; mi++) {
        long rr = row0 + mW + mi * 16 + gid;
        #pragma unroll
        for (int ni = 0; ni < 8; ni++) {
            long c = col0 + nW + ni * 8 + 2 * tg;
            float2 v0 = make_float2(acc[mi][ni][0], acc[mi][ni][1]);
            float2 v1 = make_float2(acc[mi][ni][2], acc[mi][ni][3]);
            float b0 = Aux[c], b1 = Aux[c + 1];
            v0.x = softplusf(v0.x + b0); v0.y = softplusf(v0.y + b1);
            v1.x = softplusf(v1.x + b0); v1.y = softplusf(v1.y + b1);
            *(float2*)(C + rr * N + c)       = v0;
            *(float2*)(C + (rr + 8) * N + c) = v1;
        }
    }
}

// ---------------- gemm_wx: tf32 split-K tensor GEMM ----------------
__global__ __launch_bounds__(128) void gemm_wx_tc(const float* __restrict__ A,
                                                  const float* __restrict__ W,
                                                  float* __restrict__ P)
{
    __shared__ float As[2][16][136];
    __shared__ float Ws[2][16][104];
    const int tid = threadIdx.x;
    const long row0 = (long)blockIdx.x * 128;
    const int kblk = blockIdx.y;
    const int lane = tid & 31, warp = tid >> 5;
    const int mW = (warp >> 1) * 64, nW = (warp & 1) * 48;
    const int gid = lane >> 2, tg = lane & 3;

    const int arow = tid >> 2;
    const int acg  = tid & 3;
    const float* Ap = A + (row0 + arow) * (long)DINNER + kblk * 256 + acg * 4;
    int wr[3], wc[3];
    #pragma unroll
    for (int i = 0; i < 3; i++) {
        int idx = tid + i * 128;
        wr[i] = idx / 24; wc[i] = idx - wr[i] * 24;
    }
    const float* Wp = W + (long)(kblk * 256) * XDBC;

    float4 pa[4], pw[3];
    #pragma unroll
    for (int i = 0; i < 4; i++) pa[i] = *(const float4*)(Ap + (long)i * 32 * DINNER);
    #pragma unroll
    for (int i = 0; i < 3; i++) pw[i] = *(const float4*)(Wp + (long)wr[i] * XDBC + wc[i] * 4);

    float acc[4][6][4];
    #pragma unroll
    for (int mi = 0; mi < 4; mi++)
        #pragma unroll
        for (int ni = 0; ni < 6; ni++)
            #pragma unroll
            for (int j = 0; j < 4; j++) acc[mi][ni][j] = 0.f;

    int buf = 0;
    #pragma unroll
    for (int i = 0; i < 4; i++) {
        int rr = arow + i * 32;
        float v[4] = {pa[i].x, pa[i].y, pa[i].z, pa[i].w};
        #pragma unroll
        for (int j = 0; j < 4; j++) {
            int c = acg * 4 + j;
            As[0][c][rr ^ (((c >> 2) & 3) << 3)] = to_tf32(v[j]);
        }
    }
    #pragma unroll
    for (int i = 0; i < 3; i++) {
        float4 qv = pw[i];
        qv.x = to_tf32(qv.x); qv.y = to_tf32(qv.y);
        qv.z = to_tf32(qv.z); qv.w = to_tf32(qv.w);
        *(float4*)&Ws[0][wr[i]][wc[i] * 4] = qv;
    }
    __syncthreads();

    const int KT = 256 / 16;
    for (int kt = 0; kt < KT; kt++) {
        if (kt + 1 < KT) {
            #pragma unroll
            for (int i = 0; i < 4; i++)
                pa[i] = *(const float4*)(Ap + (kt + 1) * 16 + (long)i * 32 * DINNER);
            #pragma unroll
            for (int i = 0; i < 3; i++)
                pw[i] = *(const float4*)(Wp + (long)((kt + 1) * 16 + wr[i]) * XDBC + wc[i] * 4);
        }
        #pragma unroll
        for (int ks = 0; ks < 2; ks++) {
            const int k0 = ks * 8;
            const int kA = k0 + tg, kB = k0 + tg + 4;
            const int sA = ((kA >> 2) & 3) << 3;
            const int sB = ((kB >> 2) & 3) << 3;
            float a[4][4], b[6][2];
            #pragma unroll
            for (int mi = 0; mi < 4; mi++) {
                int m = mW + mi * 16 + gid;
                a[mi][0] = As[buf][kA][m ^ sA];
                a[mi][1] = As[buf][kA][(m + 8) ^ sA];
                a[mi][2] = As[buf][kB][m ^ sB];
                a[mi][3] = As[buf][kB][(m + 8) ^ sB];
            }
            #pragma unroll
            for (int ni = 0; ni < 6; ni++) {
                int n = nW + ni * 8 + gid;
                b[ni][0] = Ws[buf][kA][n];
                b[ni][1] = Ws[buf][kB][n];
            }
            #pragma unroll
            for (int mi = 0; mi < 4; mi++)
                #pragma unroll
                for (int ni = 0; ni < 6; ni++)
                    mma_tf32(acc[mi][ni], a[mi], b[ni]);
        }
        if (kt + 1 < KT) {
            int nb = buf ^ 1;
            #pragma unroll
            for (int i = 0; i < 4; i++) {
                int rr = arow + i * 32;
                float v[4] = {pa[i].x, pa[i].y, pa[i].z, pa[i].w};
                #pragma unroll
                for (int j = 0; j < 4; j++) {
                    int c = acg * 4 + j;
                    As[nb][c][rr ^ (((c >> 2) & 3) << 3)] = to_tf32(v[j]);
                }
            }
            #pragma unroll
            for (int i = 0; i < 3; i++) {
                float4 qv = pw[i];
                qv.x = to_tf32(qv.x); qv.y = to_tf32(qv.y);
                qv.z = to_tf32(qv.z); qv.w = to_tf32(qv.w);
                *(float4*)&Ws[nb][wr[i]][wc[i] * 4] = qv;
            }
            __syncthreads();
            buf = nb;
        }
    }

    float* Pb = P + (size_t)kblk * NTOK * XDBC;
    #pragma unroll
    for (int mi = 0; mi < 4; mi++) {
        long rr = row0 + mW + mi * 16 + gid;
        #pragma unroll
        for (int ni = 0; ni < 6; ni++) {
            long c = nW + ni * 8 + 2 * tg;
            *(float2*)(Pb + rr * XDBC + c)       = make_float2(acc[mi][ni][0], acc[mi][ni][1]);
            *(float2*)(Pb + (rr + 8) * XDBC + c) = make_float2(acc[mi][ni][2], acc[mi][ni][3]);
        }
    }
}

__global__ __launch_bounds__(256) void wx_reduce(const float* __restrict__ P,
                                                 float* __restrict__ C)
{
    size_t i = (size_t)blockIdx.x * 256 + threadIdx.x;
    const float4* p = (const float4*)P;
    const size_t stride = (size_t)NTOK * XDBC / 4;
    float4 s = p[i];
    #pragma unroll
    for (int k = 1; k < WX_SPLIT; k++) {
        float4 t = p[i + (size_t)k * stride];
        s.x += t.x; s.y += t.y; s.z += t.z; s.w += t.w;
    }
    ((float4*)C)[i] = s;
}

// ---------------- selective scan, shuffle-free (bf16 y output) ----------------
// h-recurrence per (d, n) thread unchanged; per-step the product h*C goes to
// smem (conflict-free STS), and a per-chunk phase-B reduction (LDS.128 + FADD)
// replaces the 4-shfl butterfly that dominated the old kernel's issue budget.
__global__ __launch_bounds__(128) void scan_kernel(const float* __restrict__ delta,
                                                   const float* __restrict__ u,
                                                   const float* __restrict__ xdbc,
                                                   const float* __restrict__ xr,
                                                   const float* __restrict__ A_log,
                                                   const float* __restrict__ Dp,
                                                   __nv_bfloat16* __restrict__ y)
{
    __shared__ float sd[64][8], su[64][8], ybuf[64][8];
    __shared__ float sbc[64][32];
    __shared__ float sp[64][132];       // h*C products, padded row stride
    __shared__ float sD[8];

    int b     = blockIdx.x >> 8;
    int dbase = (blockIdx.x & 255) * 8;
    int tid   = threadIdx.x;
    int lane  = tid & 31, w = tid >> 5;
    int dloc  = 2 * w + (lane >> 4);
    int n     = lane & 15;
    int d     = dbase + dloc;

    float Ac = -expf(A_log[d * DSTATE + n]);
    if (tid < 8) sD[tid] = Dp[dbase + tid];

    // phase-B output mapping: (tl, dl) spread so LDS.128 conflicts are <=2-way
    int pb_tl0 = w * 8 + (lane & 7);
    int pb_dl0 = lane >> 3;

    float h = 0.0f;
    long tokbase = (long)b * NT;

    for (int c = 0; c < NT / 64; c++) {
        int t0 = c * 64;
        for (int i = tid; i < 512; i += 128) {
            int tl = i >> 3, dl = i & 7;
            long g = (tokbase + t0 + tl) * (long)DINNER + dbase + dl;
            sd[tl][dl] = delta[g];
            su[tl][dl] = u[g];
        }
        for (int i = tid; i < 2048; i += 128) {
            int tl = i >> 5, cc = i & 31;
            sbc[tl][cc] = xdbc[(tokbase + t0 + tl) * (long)XDBC + DTRANK + cc];
        }
        __syncthreads();

        // phase A: serial recurrence; store h*C (no shuffles)
        #pragma unroll 4
        for (int tl = 0; tl < 64; tl++) {
            float dlt = sd[tl][dloc];
            float uu  = su[tl][dloc];
            float a   = __expf(dlt * Ac);
            h = fmaf(a, h, dlt * uu * sbc[tl][n]);
            sp[tl][dloc * 16 + n] = h * sbc[tl][16 + n];
        }
        __syncthreads();

        // phase B: reduce 16 states per (tl, dl) -> ybuf
        #pragma unroll
        for (int j = 0; j < 4; j++) {
            int tl = pb_tl0 + (j >> 1) * 32;
            int dl = pb_dl0 + (j & 1) * 4;
            const float* row = &sp[tl][dl * 16];
            float4 v0 = *(const float4*)(row);
            float4 v1 = *(const float4*)(row + 4);
            float4 v2 = *(const float4*)(row + 8);
            float4 v3 = *(const float4*)(row + 12);
            float s01 = (v0.x + v0.y) + (v0.z + v0.w);
            float s23 = (v1.x + v1.y) + (v1.z + v1.w);
            float s45 = (v2.x + v2.y) + (v2.z + v2.w);
            float s67 = (v3.x + v3.y) + (v3.z + v3.w);
            ybuf[tl][dl] = (s01 + s23) + (s45 + s67);
        }
        __syncthreads();

        // coalesced fused epilogue flush (res read directly from xr)
        for (int i = tid; i < 512; i += 128) {
            int tl = i >> 3, dl = i & 7;
            float uu = su[tl][dl];
            float r  = xr[(tokbase + t0 + tl) * (long)(2*DINNER) + DINNER + dbase + dl];
            float yy = (ybuf[tl][dl] + uu * sD[dl]) * (r / (1.0f + __expf(-r)));
            y[(tokbase + t0 + tl) * (long)DINNER + dbase + dl] = __float2bfloat16(yy);
        }
        __syncthreads();
    }
}

// ---------------- launch ----------------
extern "C" void kernel_launch(void* const* d_in, const int* in_sizes, int n_in,
                              void* d_out, int out_size)
{
    (void)in_sizes; (void)n_in; (void)out_size;
    const float* x      = (const float*)d_in[0];
    const float* norm_w = (const float*)d_in[1];
    const float* w_in   = (const float*)d_in[2];
    const float* conv_w = (const float*)d_in[3];
    const float* conv_b = (const float*)d_in[4];
    const float* w_x    = (const float*)d_in[5];
    const float* w_dt   = (const float*)d_in[6];
    const float* b_dt   = (const float*)d_in[7];
    const float* A_log  = (const float*)d_in[8];
    const float* Dp     = (const float*)d_in[9];
    const float* w_out  = (const float*)d_in[10];
    float* out = (float*)d_out;

    __nv_bfloat16* p_xnbf  = 0;
    __nv_bfloat16* p_ybf   = 0;
    __nv_bfloat16* p_winT  = 0;
    __nv_bfloat16* p_woutT = 0;
    float* p_xr    = 0;
    float* p_u     = 0;
    float* p_xdbc  = 0;
    float* p_delta = 0;
    float* p_part  = 0;
    cudaGetSymbolAddress((void**)&p_xnbf,  g_xn_bf);
    cudaGetSymbolAddress((void**)&p_xr,    g_xr);
    cudaGetSymbolAddress((void**)&p_u,     g_u);
    cudaGetSymbolAddress((void**)&p_xdbc,  g_xdbc);
    cudaGetSymbolAddress((void**)&p_delta, g_delta);
    cudaGetSymbolAddress((void**)&p_ybf,   g_y_bf);
    cudaGetSymbolAddress((void**)&p_part,  g_part);
    cudaGetSymbolAddress((void**)&p_winT,  g_winT);
    cudaGetSymbolAddress((void**)&p_woutT, g_woutT);

    const int SMEM_GEMM = 3 * 32768;   // 96KB dynamic
    cudaFuncSetAttribute(gemm_cp<0>, cudaFuncAttributeMaxDynamicSharedMemorySize, SMEM_GEMM);
    cudaFuncSetAttribute(gemm_cp<1>, cudaFuncAttributeMaxDynamicSharedMemorySize, SMEM_GEMM);

    // 1. rmsnorm -> bf16 xn
    rms_kernel<<<NTOK, 256>>>(x, norm_w, p_xnbf);
    // 1b. weight transposes -> bf16 [N][K]
    transpose_bf<<<dim3((2*DINNER)/32, DMODEL/32), 256>>>(w_in, p_winT, DMODEL, 2*DINNER);
    transpose_bf<<<dim3(DMODEL/32, DINNER/32), 256>>>(w_out, p_woutT, DINNER, DMODEL);
    // 2. xr = xn @ w_in   [bf16 cp.async + ldmatrix, early prefetch]
    gemm_cp<0><<<dim3((2*DINNER)/128, NTOK/128), 256, SMEM_GEMM>>>(
        p_xnbf, p_winT, (const float*)0, p_xr, DMODEL, 2*DINNER);
    // 3. u = silu(depthwise_conv(xr[:, :2048]) + conv_b)
    conv_kernel<<<(NTOK*DINNER)/256, 256>>>(p_xr, conv_w, conv_b, p_u);
    // 4. xdbc = u @ w_x   [tf32 split-K + reduce]
    gemm_wx_tc<<<dim3(NTOK/128, WX_SPLIT), 128>>>(p_u, w_x, p_part);
    wx_reduce<<<(NTOK*XDBC/4)/256, 256>>>(p_part, p_xdbc);
    // 5. delta = softplus(dt @ w_dt + b_dt)   [tf32 mma, K=64]
    gemm_dt_tc<<<dim3(DINNER/128, NTOK/128), 256>>>(p_xdbc, w_dt, b_dt, p_delta, DTRANK, DINNER, XDBC);
    // 6. selective scan (shuffle-free) + gating -> bf16 y
    scan_kernel<<<NB*256, 128>>>(p_delta, p_u, p_xdbc, p_xr, A_log, Dp, p_ybf);
    // 7. out = y @ w_out + x   [bf16 cp.async + ldmatrix + residual]
    gemm_cp<1><<<dim3(DMODEL/128, NTOK/128), 256, SMEM_GEMM>>>(
        p_ybf, p_woutT, x, out, DINNER, DMODEL);
}